// round 14
// baseline (speedup 1.0000x reference)
#include <cuda_runtime.h>
#include <cuda_fp16.h>
#include <cstdint>

// Problem constants: B=4, C=256, H=W=64, K=7, GROUPS=16, GC=16, CR=64
#define HW   4096
#define WDIM 64

typedef unsigned long long ull;

// Scratch (static device globals — no allocs):
__device__ ull    g_w1d[256 * 64];          // w1 BN-folded, f32x2-duplicated [r][m]
__device__ float  g_b1f[64];                // folded conv1 bias
__device__ __half g_xh [4 * 32 * 128 * 64]; // x fp16, SW128 tiles keyed by spatial 16x8 tile
__device__ __half g_w2g[16 * 64 * 64];      // w2 fp16 per-group [64k pad][64r], SW128

__device__ __forceinline__ ull pack2(float lo, float hi) {
    ull r; asm("mov.b64 %0, {%1, %2};" : "=l"(r) : "f"(lo), "f"(hi)); return r;
}
__device__ __forceinline__ void unpack2(ull v, float &lo, float &hi) {
    asm("mov.b64 {%0, %1}, %2;" : "=f"(lo), "=f"(hi) : "l"(v));
}
__device__ __forceinline__ void fma2(ull &d, ull a, ull b) {
    asm("fma.rn.f32x2 %0, %1, %2, %0;" : "+l"(d) : "l"(a), "l"(b));
}
__device__ __forceinline__ unsigned smem_u32(const void* p) {
    return (unsigned)__cvta_generic_to_shared(p);
}
__device__ __forceinline__ void cp_async16(unsigned dst, const void* src) {
    asm volatile("cp.async.cg.shared.global [%0], [%1], 16;" :: "r"(dst), "l"(src));
}
__device__ __forceinline__ void cp_async16z(unsigned dst, const void* src, int sz) {
    asm volatile("cp.async.cg.shared.global [%0], [%1], 16, %2;"
                 :: "r"(dst), "l"(src), "r"(sz));
}
__device__ __forceinline__ void cp_async4(unsigned dst, const void* src) {
    asm volatile("cp.async.ca.shared.global [%0], [%1], 4;" :: "r"(dst), "l"(src));
}
__device__ __forceinline__ void cp_commit() {
    asm volatile("cp.async.commit_group;");
}

// ---- mma.sync (sm_80-era path: legal on plain sm_103 PTX target) ----
__device__ __forceinline__ void ldsm4(uint32_t* r, uint32_t addr) {
    asm volatile("ldmatrix.sync.aligned.m8n8.x4.shared.b16 {%0,%1,%2,%3}, [%4];"
                 : "=r"(r[0]), "=r"(r[1]), "=r"(r[2]), "=r"(r[3]) : "r"(addr));
}
__device__ __forceinline__ void mma16816(float* c, const uint32_t* a,
                                         uint32_t b0, uint32_t b1) {
    asm volatile("mma.sync.aligned.m16n8k16.row.col.f32.f16.f16.f32 "
                 "{%0,%1,%2,%3}, {%4,%5,%6,%7}, {%8,%9}, {%0,%1,%2,%3};"
                 : "+f"(c[0]), "+f"(c[1]), "+f"(c[2]), "+f"(c[3])
                 : "r"(a[0]), "r"(a[1]), "r"(a[2]), "r"(a[3]), "r"(b0), "r"(b1));
}

static __device__ __forceinline__ uint32_t sw128(uint32_t off) {
    return off ^ ((off >> 3) & 0x70);
}

// ---------------------------------------------------------------------------
// Kernel 0: prep — BN-fold + f32x2-duplicate w1; w2 -> fp16 per-group SW128
// tiles (k padded to 64). Grid 256 x 256.
// ---------------------------------------------------------------------------
__global__ __launch_bounds__(256)
void prep_kernel(const float* __restrict__ w1,
                 const float* __restrict__ gamma,
                 const float* __restrict__ beta,
                 const float* __restrict__ mean,
                 const float* __restrict__ var,
                 const float* __restrict__ w2)
{
    int idx = blockIdx.x * 256 + threadIdx.x;

    if (idx < 64) {
        float inv = gamma[idx] * rsqrtf(var[idx] + 1e-5f);
        g_b1f[idx] = beta[idx] - mean[idx] * inv;
    }
    if (idx < 64 * 256) {                 // w1d[r][m] = dup(w1[m][r] * inv[m])
        int r = idx >> 6, m = idx & 63;
        float inv = gamma[m] * rsqrtf(var[m] + 1e-5f);
        float v = w1[m * 256 + r] * inv;
        g_w1d[idx] = pack2(v, v);
    }
    if (idx < 16 * 64 * 64) {             // per-group B tile [k pad 64][r 64], SW128
        int g = idx >> 12;
        int rem = idx & 4095;
        int k = rem >> 6, r = rem & 63;
        float v = (k < 49) ? w2[(g * 49 + k) * 64 + r] : 0.f;
        uint32_t off = sw128((uint32_t)(k * 128 + r * 2));
        g_w2g[g * 4096 + (off >> 1)] = __float2half(v);
    }
}

// ---------------------------------------------------------------------------
// Kernel 1: conv1 (1x1, 256->64, BN folded) + ReLU -> g_xh (fp16, swizzled,
// spatial-tile-major). 32-px tiles, 128 threads, grid (128,4)=512, 2 CTA/SM.
// Double-buffered (w1d blk 32K + guide blk 9.2K); no in-loop packs.
// ---------------------------------------------------------------------------
#define C1_W1OFF(i) ((i) * 32768)                  // 2 x 32768 B
#define C1_GOFF(i)  (65536 + (i) * 9216)           // 2 x 9216 B
#define C1_SIZE     83968

__device__ __forceinline__ void c1_prefetch(char* csm, int buf,
        const float* __restrict__ guide, int b, int pix0, int r0, int tid)
{
    const ull* wsrc = g_w1d + r0 * 64;
    unsigned wdst = smem_u32(csm + C1_W1OFF(buf));
    #pragma unroll
    for (int i = tid; i < 2048; i += 128)
        cp_async16(wdst + i * 16, wsrc + i * 2);
    unsigned gdst = smem_u32(csm + C1_GOFF(buf));
    #pragma unroll
    for (int i = tid; i < 512; i += 128) {
        int rr = i >> 3, c = (i & 7) * 4;
        cp_async16(gdst + (rr * 36 + c) * 4,
                   guide + (size_t)(b * 256 + r0 + rr) * HW + pix0 + c);
    }
}

__global__ __launch_bounds__(128, 2)
void conv1_kernel(const float* __restrict__ guide)
{
    extern __shared__ char csm[];

    const int tid  = threadIdx.x;
    const int b    = blockIdx.y;
    const int pix0 = blockIdx.x * 32;
    const int mq = tid >> 3, pq = tid & 7;
    const int m0 = mq * 4,   p0 = pq * 4;

    c1_prefetch(csm, 0, guide, b, pix0, 0, tid);   cp_commit();
    c1_prefetch(csm, 1, guide, b, pix0, 64, tid);  cp_commit();

    ull acc[4][2];
    #pragma unroll
    for (int i = 0; i < 4; i++) {
        float bv = g_b1f[m0 + i];
        ull bp = pack2(bv, bv);
        acc[i][0] = bp; acc[i][1] = bp;
    }

    for (int blk = 0; blk < 4; blk++) {
        if (blk < 3) asm volatile("cp.async.wait_group 1;");
        else         asm volatile("cp.async.wait_group 0;");
        __syncthreads();

        const ull*   wb  = (const ull*)(csm + C1_W1OFF(blk & 1));
        const float* gsh = (const float*)(csm + C1_GOFF(blk & 1));

        #pragma unroll 8
        for (int rr = 0; rr < 64; rr++) {
            ulonglong2 xv = *(const ulonglong2*)&gsh[rr * 36 + p0];
            ulonglong2 wA = *(const ulonglong2*)&wb[rr * 64 + m0];
            ulonglong2 wB = *(const ulonglong2*)&wb[rr * 64 + m0 + 2];
            fma2(acc[0][0], xv.x, wA.x); fma2(acc[0][1], xv.y, wA.x);
            fma2(acc[1][0], xv.x, wA.y); fma2(acc[1][1], xv.y, wA.y);
            fma2(acc[2][0], xv.x, wB.x); fma2(acc[2][1], xv.y, wB.x);
            fma2(acc[3][0], xv.x, wB.y); fma2(acc[3][1], xv.y, wB.y);
        }
        __syncthreads();

        if (blk + 2 < 4) {
            c1_prefetch(csm, blk & 1, guide, b, pix0, (blk + 2) * 64, tid);
            cp_commit();
        }
    }

    // epilogue: relu, write fp16 spatial-tile-major swizzled tiles
    const int yrow  = pix0 >> 6;
    const int xbase = pix0 & 63;
    float vv[4][4];
    #pragma unroll
    for (int i = 0; i < 4; i++) {
        unpack2(acc[i][0], vv[i][0], vv[i][1]);
        unpack2(acc[i][1], vv[i][2], vv[i][3]);
        #pragma unroll
        for (int j = 0; j < 4; j++) vv[i][j] = fmaxf(vv[i][j], 0.f);
    }
    #pragma unroll
    for (int j = 0; j < 4; j++) {
        int col   = xbase + p0 + j;
        int tile  = (yrow >> 4) * 8 + (col >> 3);
        int inner = (yrow & 15) * 8 + (col & 7);
        uint32_t off = sw128((uint32_t)(inner * 128 + m0 * 2));
        __half2* dst = (__half2*)(g_xh + (size_t)(b * 32 + tile) * 8192 + (off >> 1));
        dst[0] = __floats2half2_rn(vv[0][j], vv[1][j]);
        dst[1] = __floats2half2_rn(vv[2][j], vv[3][j]);
    }
}

// ---------------------------------------------------------------------------
// Kernel 2: FUSED conv2-MMA + 7x7 dynamic aggregation + residual.
// CTA = (group, 16x8 tile, batch); 256 threads; 48.5 KB smem -> 4 CTA/SM.
// wgt_sh ALIASES the A/B staging buffers (dead after the fragment loop;
// guarded by a syncthreads between last ldsm and the scatter).
// ---------------------------------------------------------------------------
#define F_BIAS 0
#define F_A    1024                      // 16384 B (aliased by wgt later)
#define F_B    17408                     // 8192 B  (aliased by wgt later)
#define F_WGT  1024                      // 49*132*4 = 25872 B, ends 26896
#define F_F    26896                     // 16*356*4 = 22784 B
#define F_SIZE 49680
#define FRS 16
#define FCH 356
#define WGS 132                          // wgt_sh row stride (floats)

__global__ __launch_bounds__(256, 4)
void fused2_kernel(const float* __restrict__ feat,
                   const float* __restrict__ b2,
                   float* __restrict__ out)
{
    extern __shared__ char smem[];
    const unsigned sb = smem_u32(smem);
    float* f_sh   = (float*)(smem + F_F);
    float* wgt_sh = (float*)(smem + F_WGT);
    const float* bias_s = (const float*)smem;

    const int tid  = threadIdx.x;
    const int g    = blockIdx.x;
    const int tile = blockIdx.y;
    const int b    = blockIdx.z;
    const int y0 = (tile >> 3) * 16;
    const int x0 = (tile & 7) * 8;
    const int w    = tid >> 5;
    const int lane = tid & 31;

    // ---- group 0: bias + A (x tile) + B (w2 group tile)
    if (tid < 49)
        cp_async4(sb + F_BIAS + tid * 4, b2 + g * 49 + tid);
    {
        const __half* asrc = g_xh + (size_t)(b * 32 + tile) * 8192;
        #pragma unroll
        for (int i = tid; i < 1024; i += 256)
            cp_async16(sb + F_A + i * 16, asrc + i * 8);
        const __half* bsrc = g_w2g + g * 4096;
        #pragma unroll
        for (int i = tid; i < 512; i += 256)
            cp_async16(sb + F_B + i * 16, bsrc + i * 8);
    }
    cp_commit();

    // ---- group 1: feature tile + halo (aligned 16B chunks, zfill OOB)
    {
        const float* fch0 = feat + (size_t)(b * 256 + g * 16) * HW;
        for (int i = tid; i < 1408; i += 256) {
            int c   = i / 88;
            int rem = i - c * 88;
            int yy  = rem >> 2;
            int q   = rem & 3;
            int gy  = y0 + yy - 3;
            int gx0 = x0 - 4 + q * 4;
            bool ok = ((unsigned)gy < 64u) && ((unsigned)gx0 <= 60u);
            const float* src = fch0 + (size_t)c * HW + (ok ? gy * WDIM + gx0 : 0);
            cp_async16z(sb + F_F + (c * FCH + yy * FRS + q * 4) * 4, src, ok ? 16 : 0);
        }
    }
    cp_commit();

    asm volatile("cp.async.wait_group 1;");   // A/B/bias ready; f in flight
    __syncthreads();

    // ---- MMA phase: wgt = w2_g @ x + b2 (in-register, bias-seeded)
    {
        const int kc = (lane & 3) * 2;
        float acc[8][4];
        #pragma unroll
        for (int nt = 0; nt < 8; nt++) {
            int k = nt * 8 + kc;
            float be = (k < 49) ? bias_s[k] : 0.f;
            float bo = (k + 1 < 49) ? bias_s[k + 1] : 0.f;
            acc[nt][0] = be; acc[nt][1] = bo;
            acc[nt][2] = be; acc[nt][3] = bo;
        }

        const int lrow = lane & 15;
        const int lcb  = lane >> 4;
        #pragma unroll
        for (int ks = 0; ks < 4; ks++) {
            uint32_t a[4];
            {
                uint32_t off = sw128((uint32_t)((w * 16 + lrow) * 128 + ks * 32 + lcb * 16));
                ldsm4(a, sb + F_A + off);
            }
            #pragma unroll
            for (int ntp = 0; ntp < 4; ntp++) {
                uint32_t bf[4];
                uint32_t off = sw128((uint32_t)((ntp * 16 + lrow) * 128 + ks * 32 + lcb * 16));
                ldsm4(bf, sb + F_B + off);
                mma16816(acc[2 * ntp],     a, bf[0], bf[2]);
                mma16816(acc[2 * ntp + 1], a, bf[1], bf[3]);
            }
        }

        __syncthreads();   // all ldsm complete before wgt aliases A/B

        // scatter fragments to wgt_sh[k][inner], row stride 132 (conflict-free)
        const int inner0 = w * 16 + (lane >> 2);
        #pragma unroll
        for (int nt = 0; nt < 7; nt++) {
            int k = nt * 8 + kc;
            float* row = wgt_sh + k * WGS;
            if (k < 49)     { row[inner0] = acc[nt][0];       row[inner0 + 8] = acc[nt][2]; }
            if (k + 1 < 49) { row[WGS + inner0] = acc[nt][1]; row[WGS + inner0 + 8] = acc[nt][3]; }
        }
    }

    asm volatile("cp.async.wait_group 0;");   // f complete (hidden under MMA)
    __syncthreads();

    // ---- aggregation phase (proven, wgt stride 132)
    {
        const int rowA = 2 * w + (lane >> 4);
        const int c    = lane & 15;

        const float* fbase = f_sh + c * FCH;
        const float* wbase = wgt_sh + rowA * 8;

        ull accp[4] = {0ull, 0ull, 0ull, 0ull};

        #pragma unroll 1
        for (int di = 0; di < 7; di++) {
            const float* frow = fbase + (rowA + di) * FRS;
            float4 A = *(const float4*)(frow);
            float4 B = *(const float4*)(frow + 4);
            float4 C = *(const float4*)(frow + 8);
            float4 D = *(const float4*)(frow + 12);
            ull fra[7];
            fra[1] = pack2(A.z, A.w); fra[2] = pack2(B.x, B.y);
            fra[3] = pack2(B.z, B.w); fra[4] = pack2(C.x, C.y);
            fra[5] = pack2(C.z, C.w); fra[6] = pack2(D.x, D.y);
            ull frb[7];
            frb[0] = pack2(A.y, A.z); frb[1] = pack2(A.w, B.x);
            frb[2] = pack2(B.y, B.z); frb[3] = pack2(B.w, C.x);
            frb[4] = pack2(C.y, C.z); frb[5] = pack2(C.w, D.x);
            frb[6] = pack2(D.y, D.z);

            #pragma unroll
            for (int dj = 0; dj < 7; dj += 2) {
                int k = di * 7 + dj;
                ulonglong2 wv01 = *(const ulonglong2*)(wbase + k * WGS);
                ulonglong2 wv23 = *(const ulonglong2*)(wbase + k * WGS + 4);
                int s = dj >> 1;
                fma2(accp[0], wv01.x, frb[s]);
                fma2(accp[1], wv01.y, frb[s + 1]);
                fma2(accp[2], wv23.x, frb[s + 2]);
                fma2(accp[3], wv23.y, frb[s + 3]);
            }
            #pragma unroll
            for (int dj = 1; dj < 7; dj += 2) {
                int k = di * 7 + dj;
                ulonglong2 wv01 = *(const ulonglong2*)(wbase + k * WGS);
                ulonglong2 wv23 = *(const ulonglong2*)(wbase + k * WGS + 4);
                int s = (dj + 1) >> 1;
                fma2(accp[0], wv01.x, fra[s]);
                fma2(accp[1], wv01.y, fra[s + 1]);
                fma2(accp[2], wv23.x, fra[s + 2]);
                fma2(accp[3], wv23.y, fra[s + 3]);
            }
        }

        float acc[8];
        unpack2(accp[0], acc[0], acc[1]);
        unpack2(accp[1], acc[2], acc[3]);
        unpack2(accp[2], acc[4], acc[5]);
        unpack2(accp[3], acc[6], acc[7]);
        #pragma unroll
        for (int j = 0; j < 8; j++)
            acc[j] += fbase[(rowA + 3) * FRS + j + 4];

        float* op = &out[(size_t)(b * 256 + g * 16 + c) * HW + (y0 + rowA) * WDIM + x0];
        *(float4*)(op)     = make_float4(acc[0], acc[1], acc[2], acc[3]);
        *(float4*)(op + 4) = make_float4(acc[4], acc[5], acc[6], acc[7]);
    }
}

// ---------------------------------------------------------------------------
extern "C" void kernel_launch(void* const* d_in, const int* in_sizes, int n_in,
                              void* d_out, int out_size)
{
    const float* feat  = (const float*)d_in[0];
    const float* guide = (const float*)d_in[1];
    const float* w1    = (const float*)d_in[2];
    const float* gamma = (const float*)d_in[3];
    const float* beta  = (const float*)d_in[4];
    const float* mean  = (const float*)d_in[5];
    const float* var   = (const float*)d_in[6];
    const float* w2    = (const float*)d_in[7];
    const float* b2    = (const float*)d_in[8];
    float* out = (float*)d_out;

    prep_kernel<<<256, 256>>>(w1, gamma, beta, mean, var, w2);

    cudaFuncSetAttribute(conv1_kernel,
                         cudaFuncAttributeMaxDynamicSharedMemorySize, C1_SIZE);
    conv1_kernel<<<dim3(128, 4), 128, C1_SIZE>>>(guide);

    cudaFuncSetAttribute(fused2_kernel,
                         cudaFuncAttributeMaxDynamicSharedMemorySize, F_SIZE);
    fused2_kernel<<<dim3(16, 32, 4), 256, F_SIZE>>>(feat, b2, out);
}

// round 17
// speedup vs baseline: 1.6735x; 1.6735x over previous
#include <cuda_runtime.h>
#include <cuda_fp16.h>
#include <cstdint>

// Problem constants: B=4, C=256, H=W=64, K=7, GROUPS=16, GC=16, CR=64
#define HW   4096
#define WDIM 64

typedef unsigned long long ull;

// Scratch (static device globals — no allocs):
__device__ float  g_w1f[64 * 256];          // w1 transposed [r][m], BN-folded
__device__ float  g_b1f[64];                // folded conv1 bias
__device__ __half g_xh [4 * 32 * 128 * 64]; // x fp16, SW128 tiles keyed by spatial 16x8 tile
__device__ __half g_w2g[16 * 64 * 64];      // w2 fp16 per-group [64k pad][64r], SW128

__device__ __forceinline__ ull pack2(float lo, float hi) {
    ull r; asm("mov.b64 %0, {%1, %2};" : "=l"(r) : "f"(lo), "f"(hi)); return r;
}
__device__ __forceinline__ void unpack2(ull v, float &lo, float &hi) {
    asm("mov.b64 {%0, %1}, %2;" : "=f"(lo), "=f"(hi) : "l"(v));
}
__device__ __forceinline__ void fma2(ull &d, ull a, ull b) {
    asm("fma.rn.f32x2 %0, %1, %2, %0;" : "+l"(d) : "l"(a), "l"(b));
}
__device__ __forceinline__ unsigned smem_u32(const void* p) {
    return (unsigned)__cvta_generic_to_shared(p);
}
__device__ __forceinline__ void cp_async16(unsigned dst, const void* src) {
    asm volatile("cp.async.cg.shared.global [%0], [%1], 16;" :: "r"(dst), "l"(src));
}
__device__ __forceinline__ void cp_async16z(unsigned dst, const void* src, int sz) {
    asm volatile("cp.async.cg.shared.global [%0], [%1], 16, %2;"
                 :: "r"(dst), "l"(src), "r"(sz));
}
__device__ __forceinline__ void cp_async4(unsigned dst, const void* src) {
    asm volatile("cp.async.ca.shared.global [%0], [%1], 4;" :: "r"(dst), "l"(src));
}
__device__ __forceinline__ void cp_commit() {
    asm volatile("cp.async.commit_group;");
}

// ---- mma.sync (sm_80-era path: legal on plain sm_103 PTX target) ----
__device__ __forceinline__ void ldsm4(uint32_t* r, uint32_t addr) {
    asm volatile("ldmatrix.sync.aligned.m8n8.x4.shared.b16 {%0,%1,%2,%3}, [%4];"
                 : "=r"(r[0]), "=r"(r[1]), "=r"(r[2]), "=r"(r[3]) : "r"(addr));
}
__device__ __forceinline__ void mma16816(float* c, const uint32_t* a,
                                         uint32_t b0, uint32_t b1) {
    asm volatile("mma.sync.aligned.m16n8k16.row.col.f32.f16.f16.f32 "
                 "{%0,%1,%2,%3}, {%4,%5,%6,%7}, {%8,%9}, {%0,%1,%2,%3};"
                 : "+f"(c[0]), "+f"(c[1]), "+f"(c[2]), "+f"(c[3])
                 : "r"(a[0]), "r"(a[1]), "r"(a[2]), "r"(a[3]), "r"(b0), "r"(b1));
}

static __device__ __forceinline__ uint32_t sw128(uint32_t off) {
    return off ^ ((off >> 3) & 0x70);
}

// ---------------------------------------------------------------------------
// Kernel 0: prep — fold BN into w1f; w2 -> fp16 per-group SW128 tiles (k pad 64).
// Grid 256 x 256.  (R13-proven version)
// ---------------------------------------------------------------------------
__global__ __launch_bounds__(256)
void prep_kernel(const float* __restrict__ w1,
                 const float* __restrict__ gamma,
                 const float* __restrict__ beta,
                 const float* __restrict__ mean,
                 const float* __restrict__ var,
                 const float* __restrict__ w2)
{
    int idx = blockIdx.x * 256 + threadIdx.x;

    if (idx < 64) {
        float inv = gamma[idx] * rsqrtf(var[idx] + 1e-5f);
        g_b1f[idx] = beta[idx] - mean[idx] * inv;
    }
    if (idx < 64 * 256) {                 // w1f[r][m] = w1[m][r] * inv[m]
        int r = idx >> 6, m = idx & 63;
        float inv = gamma[m] * rsqrtf(var[m] + 1e-5f);
        g_w1f[idx] = w1[m * 256 + r] * inv;
    }
    if (idx < 16 * 64 * 64) {             // per-group B tile [k pad 64][r 64], SW128
        int g = idx >> 12;
        int rem = idx & 4095;
        int k = rem >> 6, r = rem & 63;
        float v = (k < 49) ? w2[(g * 49 + k) * 64 + r] : 0.f;
        uint32_t off = sw128((uint32_t)(k * 128 + r * 2));
        g_w2g[g * 4096 + (off >> 1)] = __float2half(v);
    }
}

// ---------------------------------------------------------------------------
// Kernel 1: conv1 (1x1, 256->64, BN folded) + ReLU -> g_xh (fp16, swizzled,
// spatial-tile-major). R13-proven version: 64-px tiles, 256 threads,
// grid (64,4), 2 CTA/SM, w1f staged once per CTA.
// ---------------------------------------------------------------------------
#define C1G 4352   // 64*68 floats per guide buffer

__global__ __launch_bounds__(256, 2)
void conv1_kernel(const float* __restrict__ guide)
{
    extern __shared__ float csm[];
    float* w1s = csm;                                    // [256 r][64 m] 64 KB
    float* gb[2] = { csm + 16384, csm + 16384 + C1G };

    const int tid   = threadIdx.x;
    const int b     = blockIdx.y;
    const int yrow  = blockIdx.x;                 // image row
    const int gpix0 = yrow * 64;
    const int mq = tid >> 4, pq = tid & 15;
    const int m0 = mq * 4,   p0 = pq * 4;

    #pragma unroll
    for (int i = tid; i < 4096; i += 256)
        cp_async16(smem_u32(w1s + i * 4), g_w1f + i * 4);
    #pragma unroll
    for (int i = tid; i < 1024; i += 256) {
        int rr = i >> 4, px4 = (i & 15) * 4;
        cp_async16(smem_u32(gb[0] + rr * 68 + px4),
                   guide + (size_t)(b * 256 + rr) * HW + gpix0 + px4);
    }
    cp_commit();
    #pragma unroll
    for (int i = tid; i < 1024; i += 256) {
        int rr = i >> 4, px4 = (i & 15) * 4;
        cp_async16(smem_u32(gb[1] + rr * 68 + px4),
                   guide + (size_t)(b * 256 + 64 + rr) * HW + gpix0 + px4);
    }
    cp_commit();

    ull acc[4][2];
    #pragma unroll
    for (int i = 0; i < 4; i++) {
        float bv = g_b1f[m0 + i];
        ull bp = pack2(bv, bv);
        acc[i][0] = bp; acc[i][1] = bp;
    }

    for (int blk = 0; blk < 4; blk++) {
        if (blk < 3) asm volatile("cp.async.wait_group 1;");
        else         asm volatile("cp.async.wait_group 0;");
        __syncthreads();

        const float* wb  = w1s + blk * 64 * 64;
        const float* gsh = gb[blk & 1];

        #pragma unroll 8
        for (int rr = 0; rr < 64; rr++) {
            float4 w4 = *(const float4*)&wb[rr * 64 + m0];
            ulonglong2 xv = *(const ulonglong2*)&gsh[rr * 68 + p0];
            ull wp;
            wp = pack2(w4.x, w4.x); fma2(acc[0][0], xv.x, wp); fma2(acc[0][1], xv.y, wp);
            wp = pack2(w4.y, w4.y); fma2(acc[1][0], xv.x, wp); fma2(acc[1][1], xv.y, wp);
            wp = pack2(w4.z, w4.z); fma2(acc[2][0], xv.x, wp); fma2(acc[2][1], xv.y, wp);
            wp = pack2(w4.w, w4.w); fma2(acc[3][0], xv.x, wp); fma2(acc[3][1], xv.y, wp);
        }
        __syncthreads();

        if (blk + 2 < 4) {
            float* dstb = gb[blk & 1];
            #pragma unroll
            for (int i = tid; i < 1024; i += 256) {
                int rr = i >> 4, px4 = (i & 15) * 4;
                cp_async16(smem_u32(dstb + rr * 68 + px4),
                           guide + (size_t)(b * 256 + (blk + 2) * 64 + rr) * HW + gpix0 + px4);
            }
            cp_commit();
        }
    }

    // epilogue: relu, write fp16 spatial-tile-major swizzled tiles
    float vv[4][4];
    #pragma unroll
    for (int i = 0; i < 4; i++) {
        unpack2(acc[i][0], vv[i][0], vv[i][1]);
        unpack2(acc[i][1], vv[i][2], vv[i][3]);
        #pragma unroll
        for (int j = 0; j < 4; j++) vv[i][j] = fmaxf(vv[i][j], 0.f);
    }
    #pragma unroll
    for (int j = 0; j < 4; j++) {
        int col  = p0 + j;                              // 0..63
        int tile = (yrow >> 4) * 8 + (col >> 3);        // 0..31
        int inner = (yrow & 15) * 8 + (col & 7);        // 0..127
        uint32_t off = sw128((uint32_t)(inner * 128 + m0 * 2));
        __half2* dst = (__half2*)(g_xh + (size_t)(b * 32 + tile) * 8192 + (off >> 1));
        dst[0] = __floats2half2_rn(vv[0][j], vv[1][j]);
        dst[1] = __floats2half2_rn(vv[2][j], vv[3][j]);
    }
}

// ---------------------------------------------------------------------------
// Kernel 2: FUSED conv2-MMA + 7x7 dynamic aggregation + residual.
// CTA = (group, 16x8 tile, batch); 256 threads; 48.5 KB smem, target 4 CTA/SM.
// wgt_sh ALIASES the A/B staging buffers (dead after the fragment loop).
// Register trim vs R14: dead acc[7] tile (k>=56) removed entirely.
// ---------------------------------------------------------------------------
#define F_BIAS 0
#define F_A    1024                      // 16384 B (aliased by wgt later)
#define F_B    17408                     // 8192 B  (aliased by wgt later)
#define F_WGT  1024                      // 49*132*4 = 25872 B, ends 26896
#define F_F    26896                     // 16*356*4 = 22784 B
#define F_SIZE 49680
#define FRS 16
#define FCH 356
#define WGS 132                          // wgt_sh row stride (floats)

__global__ __launch_bounds__(256, 4)
void fused2_kernel(const float* __restrict__ feat,
                   const float* __restrict__ b2,
                   float* __restrict__ out)
{
    extern __shared__ char smem[];
    const unsigned sb = smem_u32(smem);
    float* f_sh   = (float*)(smem + F_F);
    float* wgt_sh = (float*)(smem + F_WGT);
    const float* bias_s = (const float*)smem;

    const int tid  = threadIdx.x;
    const int g    = blockIdx.x;
    const int tile = blockIdx.y;
    const int b    = blockIdx.z;
    const int y0 = (tile >> 3) * 16;
    const int x0 = (tile & 7) * 8;
    const int w    = tid >> 5;
    const int lane = tid & 31;

    // ---- group 0: bias + A (x tile) + B (w2 group tile)
    if (tid < 49)
        cp_async4(sb + F_BIAS + tid * 4, b2 + g * 49 + tid);
    {
        const __half* asrc = g_xh + (size_t)(b * 32 + tile) * 8192;
        #pragma unroll
        for (int i = tid; i < 1024; i += 256)
            cp_async16(sb + F_A + i * 16, asrc + i * 8);
        const __half* bsrc = g_w2g + g * 4096;
        #pragma unroll
        for (int i = tid; i < 512; i += 256)
            cp_async16(sb + F_B + i * 16, bsrc + i * 8);
    }
    cp_commit();

    // ---- group 1: feature tile + halo (aligned 16B chunks, zfill OOB)
    {
        const float* fch0 = feat + (size_t)(b * 256 + g * 16) * HW;
        for (int i = tid; i < 1408; i += 256) {
            int c   = i / 88;
            int rem = i - c * 88;
            int yy  = rem >> 2;
            int q   = rem & 3;
            int gy  = y0 + yy - 3;
            int gx0 = x0 - 4 + q * 4;
            bool ok = ((unsigned)gy < 64u) && ((unsigned)gx0 <= 60u);
            const float* src = fch0 + (size_t)c * HW + (ok ? gy * WDIM + gx0 : 0);
            cp_async16z(sb + F_F + (c * FCH + yy * FRS + q * 4) * 4, src, ok ? 16 : 0);
        }
    }
    cp_commit();

    asm volatile("cp.async.wait_group 1;");   // A/B/bias ready; f in flight
    __syncthreads();

    // ---- MMA phase: wgt = w2_g @ x + b2 (in-register, bias-seeded)
    {
        const int kc = (lane & 3) * 2;
        float acc[7][4];                      // k tiles 0..6 (k<56); k>=56 dead
        #pragma unroll
        for (int nt = 0; nt < 7; nt++) {
            int k = nt * 8 + kc;
            float be = (k < 49) ? bias_s[k] : 0.f;
            float bo = (k + 1 < 49) ? bias_s[k + 1] : 0.f;
            acc[nt][0] = be; acc[nt][1] = bo;
            acc[nt][2] = be; acc[nt][3] = bo;
        }

        const int lrow = lane & 15;
        const int lcb  = lane >> 4;
        #pragma unroll
        for (int ks = 0; ks < 4; ks++) {
            uint32_t a[4];
            {
                uint32_t off = sw128((uint32_t)((w * 16 + lrow) * 128 + ks * 32 + lcb * 16));
                ldsm4(a, sb + F_A + off);
            }
            #pragma unroll
            for (int ntp = 0; ntp < 4; ntp++) {
                uint32_t bf[4];
                uint32_t off = sw128((uint32_t)((ntp * 16 + lrow) * 128 + ks * 32 + lcb * 16));
                ldsm4(bf, sb + F_B + off);
                mma16816(acc[2 * ntp], a, bf[0], bf[2]);
                if (ntp < 3)
                    mma16816(acc[2 * ntp + 1], a, bf[1], bf[3]);  // acc[7] dead -> skipped
            }
        }

        __syncthreads();   // all ldsm complete before wgt aliases A/B

        // scatter fragments to wgt_sh[k][inner], row stride 132 (conflict-free)
        const int inner0 = w * 16 + (lane >> 2);
        #pragma unroll
        for (int nt = 0; nt < 7; nt++) {
            int k = nt * 8 + kc;
            float* row = wgt_sh + k * WGS;
            if (k < 49)     { row[inner0] = acc[nt][0];       row[inner0 + 8] = acc[nt][2]; }
            if (k + 1 < 49) { row[WGS + inner0] = acc[nt][1]; row[WGS + inner0 + 8] = acc[nt][3]; }
        }
    }

    asm volatile("cp.async.wait_group 0;");   // f complete (hidden under MMA)
    __syncthreads();

    // ---- aggregation phase (proven, wgt stride 132)
    {
        const int rowA = 2 * w + (lane >> 4);
        const int c    = lane & 15;

        const float* fbase = f_sh + c * FCH;
        const float* wbase = wgt_sh + rowA * 8;

        ull accp[4] = {0ull, 0ull, 0ull, 0ull};

        #pragma unroll 1
        for (int di = 0; di < 7; di++) {
            const float* frow = fbase + (rowA + di) * FRS;
            float4 A = *(const float4*)(frow);
            float4 B = *(const float4*)(frow + 4);
            float4 C = *(const float4*)(frow + 8);
            float4 D = *(const float4*)(frow + 12);
            ull fra[7];
            fra[1] = pack2(A.z, A.w); fra[2] = pack2(B.x, B.y);
            fra[3] = pack2(B.z, B.w); fra[4] = pack2(C.x, C.y);
            fra[5] = pack2(C.z, C.w); fra[6] = pack2(D.x, D.y);
            ull frb[7];
            frb[0] = pack2(A.y, A.z); frb[1] = pack2(A.w, B.x);
            frb[2] = pack2(B.y, B.z); frb[3] = pack2(B.w, C.x);
            frb[4] = pack2(C.y, C.z); frb[5] = pack2(C.w, D.x);
            frb[6] = pack2(D.y, D.z);

            #pragma unroll
            for (int dj = 0; dj < 7; dj += 2) {
                int k = di * 7 + dj;
                ulonglong2 wv01 = *(const ulonglong2*)(wbase + k * WGS);
                ulonglong2 wv23 = *(const ulonglong2*)(wbase + k * WGS + 4);
                int s = dj >> 1;
                fma2(accp[0], wv01.x, frb[s]);
                fma2(accp[1], wv01.y, frb[s + 1]);
                fma2(accp[2], wv23.x, frb[s + 2]);
                fma2(accp[3], wv23.y, frb[s + 3]);
            }
            #pragma unroll
            for (int dj = 1; dj < 7; dj += 2) {
                int k = di * 7 + dj;
                ulonglong2 wv01 = *(const ulonglong2*)(wbase + k * WGS);
                ulonglong2 wv23 = *(const ulonglong2*)(wbase + k * WGS + 4);
                int s = (dj + 1) >> 1;
                fma2(accp[0], wv01.x, fra[s]);
                fma2(accp[1], wv01.y, fra[s + 1]);
                fma2(accp[2], wv23.x, fra[s + 2]);
                fma2(accp[3], wv23.y, fra[s + 3]);
            }
        }

        float acc[8];
        unpack2(accp[0], acc[0], acc[1]);
        unpack2(accp[1], acc[2], acc[3]);
        unpack2(accp[2], acc[4], acc[5]);
        unpack2(accp[3], acc[6], acc[7]);
        #pragma unroll
        for (int j = 0; j < 8; j++)
            acc[j] += fbase[(rowA + 3) * FRS + j + 4];

        float* op = &out[(size_t)(b * 256 + g * 16 + c) * HW + (y0 + rowA) * WDIM + x0];
        *(float4*)(op)     = make_float4(acc[0], acc[1], acc[2], acc[3]);
        *(float4*)(op + 4) = make_float4(acc[4], acc[5], acc[6], acc[7]);
    }
}

// ---------------------------------------------------------------------------
extern "C" void kernel_launch(void* const* d_in, const int* in_sizes, int n_in,
                              void* d_out, int out_size)
{
    const float* feat  = (const float*)d_in[0];
    const float* guide = (const float*)d_in[1];
    const float* w1    = (const float*)d_in[2];
    const float* gamma = (const float*)d_in[3];
    const float* beta  = (const float*)d_in[4];
    const float* mean  = (const float*)d_in[5];
    const float* var   = (const float*)d_in[6];
    const float* w2    = (const float*)d_in[7];
    const float* b2    = (const float*)d_in[8];
    float* out = (float*)d_out;

    prep_kernel<<<256, 256>>>(w1, gamma, beta, mean, var, w2);

    const int c1_smem = (16384 + 2 * C1G) * 4;            // 100352
    cudaFuncSetAttribute(conv1_kernel,
                         cudaFuncAttributeMaxDynamicSharedMemorySize, c1_smem);
    conv1_kernel<<<dim3(64, 4), 256, c1_smem>>>(guide);

    cudaFuncSetAttribute(fused2_kernel,
                         cudaFuncAttributeMaxDynamicSharedMemorySize, F_SIZE);
    fused2_kernel<<<dim3(16, 32, 4), 256, F_SIZE>>>(feat, b2, out);
}